// round 1
// baseline (speedup 1.0000x reference)
#include <cuda_runtime.h>
#include <math.h>

#define B_ 256
#define T_ 1024
#define V_ 96
#define H_ 128

typedef unsigned long long ull;

// Scratch (device globals: allocation-free per harness rules)
__device__ __align__(16) float g_proj[V_ * H_];          // emb @ W_ih0^T + b0  [96,128]
__device__ __align__(16) float g_y0[B_ * T_ * H_];       // layer-0 outputs
__device__ __align__(16) float g_y1[B_ * T_ * H_];       // layer-1 outputs

// packed fp32x2 FMA (Blackwell FFMA2): d = a*b + c, lanewise
__device__ __forceinline__ ull ffma2(ull a, ull b, ull c) {
    ull d;
    asm("fma.rn.f32x2 %0, %1, %2, %3;" : "=l"(d) : "l"(a), "l"(b), "l"(c));
    return d;
}
__device__ __forceinline__ float hadd(ull a) {
    float x, y;
    asm("mov.b64 {%0, %1}, %2;" : "=f"(x), "=f"(y) : "l"(a));
    return x + y;
}

// ---------------------------------------------------------------------------
// Kernel 1: projected embedding table  g_proj[v][j] = sum_h emb[v][h]*W_ih0[j][h] + b_ih0[j] + b_hh0[j]
// ---------------------------------------------------------------------------
__global__ void k_proj(const float* __restrict__ emb, const float* __restrict__ Wih0,
                       const float* __restrict__ bih0, const float* __restrict__ bhh0) {
    __shared__ float er[H_];
    int v = blockIdx.x, j = threadIdx.x;
    er[j] = emb[v * H_ + j];
    __syncthreads();
    float s = bih0[j] + bhh0[j];
    const float* wr = Wih0 + j * H_;
#pragma unroll 8
    for (int h = 0; h < H_; h++) s += er[h] * wr[h];
    g_proj[v * H_ + j] = s;
}

// ---------------------------------------------------------------------------
// Kernel 2: layer-0 recurrence. 128 CTAs x 256 threads, 2 batch elems per CTA.
// thread: j = tid&127 (output idx), kh = tid>>7 (k half). W_hh0 row-slice in regs
// as packed k-pairs. h in smem, read as 128-bit (2 k-pairs) broadcasts.
// ---------------------------------------------------------------------------
__global__ void __launch_bounds__(256, 1)
k_l0(const int* __restrict__ x, const float* __restrict__ Whh0, float* __restrict__ hid0) {
    extern __shared__ float sm[];
    float* proj_s = sm;                           // 12288 floats (48KB)
    float* h0s    = sm + 12288;                   // 256 floats  (b0: 0..127, b1: 128..255)
    float2* redA  = (float2*)(sm + 12544);        // 128 float2 (written by kh=1)
    float2* redB  = redA + 128;                   // 128 float2 (written by kh=0)

    int tid = threadIdx.x;
    int j = tid & 127, kh = tid >> 7;
    int b0 = blockIdx.x * 2, b1 = b0 + 1;

    ull w0p[32];
    const ull* Wp = (const ull*)Whh0;
    int wbase = j * 64 + kh * 32;                 // pairs (k, k+1), k = kh*64 + 2i
#pragma unroll
    for (int i = 0; i < 32; i++) w0p[i] = Wp[wbase + i];

    for (int i = tid; i < (V_ * H_) / 4; i += 256)
        ((float4*)proj_s)[i] = ((const float4*)g_proj)[i];
    h0s[tid] = 0.0f;
    __syncthreads();

    int xi0 = x[b0 * T_], xi1 = x[b1 * T_];
    for (int t = 0; t < T_; t++) {
        int nx0 = xi0, nx1 = xi1;
        if (t + 1 < T_) { nx0 = x[b0 * T_ + t + 1]; nx1 = x[b1 * T_ + t + 1]; }

        ull a0 = 0, a0b = 0, a1 = 0, a1b = 0;
        const ulonglong2* h2 = (const ulonglong2*)h0s;
        int hb = kh * 16;
#pragma unroll
        for (int i = 0; i < 16; i++) {
            ulonglong2 hv0 = h2[hb + i];
            ulonglong2 hv1 = h2[32 + hb + i];
            a0  = ffma2(w0p[2 * i],     hv0.x, a0);
            a0b = ffma2(w0p[2 * i + 1], hv0.y, a0b);
            a1  = ffma2(w0p[2 * i],     hv1.x, a1);
            a1b = ffma2(w0p[2 * i + 1], hv1.y, a1b);
        }
        float p0 = hadd(a0) + hadd(a0b);
        float p1 = hadd(a1) + hadd(a1b);

        if (kh) redA[j] = make_float2(p0, p1);
        else    redB[j] = make_float2(p0, p1);
        __syncthreads();

        if (!kh) {
            float nh = tanhf(p0 + redA[j].x + proj_s[xi0 * H_ + j]);
            h0s[j] = nh;
            g_y0[(b0 * T_ + t) * H_ + j] = nh;
            if (t == T_ - 1) hid0[b0 * H_ + j] = nh;
        } else {
            float nh = tanhf(p1 + redB[j].y + proj_s[xi1 * H_ + j]);
            h0s[128 + j] = nh;
            g_y0[(b1 * T_ + t) * H_ + j] = nh;
            if (t == T_ - 1) hid0[b1 * H_ + j] = nh;
        }
        __syncthreads();
        xi0 = nx0; xi1 = nx1;
    }
}

// ---------------------------------------------------------------------------
// Kernel 3: layer-1 recurrence with fused input projection:
//   h1 = tanh(W_ih1 * y0_t + W_hh1 * h1 + b). y0 double-buffered through smem
//   with register prefetch from global.
// ---------------------------------------------------------------------------
__global__ void __launch_bounds__(256, 1)
k_l1(const float* __restrict__ Wih1, const float* __restrict__ Whh1,
     const float* __restrict__ bih1, const float* __restrict__ bhh1,
     float* __restrict__ hid1) {
    __shared__ float bias_s[128];
    __shared__ __align__(16) float h1s[256];
    __shared__ __align__(16) float y0s[2][256];
    __shared__ float2 redA[128];
    __shared__ float2 redB[128];

    int tid = threadIdx.x;
    int j = tid & 127, kh = tid >> 7;
    int b0 = blockIdx.x * 2;
    int bb = kh, k = j;   // staging role: batch bb, element k

    ull w1p[32], w2p[32];
    int wbase = j * 64 + kh * 32;
    const ull* W1 = (const ull*)Wih1;
    const ull* W2 = (const ull*)Whh1;
#pragma unroll
    for (int i = 0; i < 32; i++) { w1p[i] = W1[wbase + i]; w2p[i] = W2[wbase + i]; }

    if (tid < 128) bias_s[tid] = bih1[tid] + bhh1[tid];
    h1s[tid] = 0.0f;
    y0s[0][tid] = g_y0[((b0 + bb) * T_ + 0) * H_ + k];
    float pf = g_y0[((b0 + bb) * T_ + 1) * H_ + k];
    __syncthreads();

    for (int t = 0; t < T_; t++) {
        const ulonglong2* h2 = (const ulonglong2*)h1s;
        const ulonglong2* y2 = (const ulonglong2*)(&y0s[t & 1][0]);
        int hb = kh * 16;
        ull aY0 = 0, aY0b = 0, aH0 = 0, aH0b = 0;
        ull aY1 = 0, aY1b = 0, aH1 = 0, aH1b = 0;
#pragma unroll
        for (int i = 0; i < 16; i++) {
            ulonglong2 yv0 = y2[hb + i];
            ulonglong2 yv1 = y2[32 + hb + i];
            ulonglong2 hv0 = h2[hb + i];
            ulonglong2 hv1 = h2[32 + hb + i];
            aY0  = ffma2(w1p[2 * i],     yv0.x, aY0);
            aY0b = ffma2(w1p[2 * i + 1], yv0.y, aY0b);
            aH0  = ffma2(w2p[2 * i],     hv0.x, aH0);
            aH0b = ffma2(w2p[2 * i + 1], hv0.y, aH0b);
            aY1  = ffma2(w1p[2 * i],     yv1.x, aY1);
            aY1b = ffma2(w1p[2 * i + 1], yv1.y, aY1b);
            aH1  = ffma2(w2p[2 * i],     hv1.x, aH1);
            aH1b = ffma2(w2p[2 * i + 1], hv1.y, aH1b);
        }
        float p0 = hadd(aY0) + hadd(aY0b) + hadd(aH0) + hadd(aH0b);
        float p1 = hadd(aY1) + hadd(aY1b) + hadd(aH1) + hadd(aH1b);

        // stage t+1 tile (other buffer), then issue prefetch for t+2
        y0s[(t + 1) & 1][tid] = pf;
        int tn = (t + 2 < T_) ? (t + 2) : (T_ - 1);
        pf = g_y0[((b0 + bb) * T_ + tn) * H_ + k];

        if (kh) redA[j] = make_float2(p0, p1);
        else    redB[j] = make_float2(p0, p1);
        __syncthreads();

        if (!kh) {
            float nh = tanhf(p0 + redA[j].x + bias_s[j]);
            h1s[j] = nh;
            g_y1[(b0 * T_ + t) * H_ + j] = nh;
            if (t == T_ - 1) hid1[b0 * H_ + j] = nh;
        } else {
            float nh = tanhf(p1 + redB[j].y + bias_s[j]);
            h1s[128 + j] = nh;
            g_y1[((b0 + 1) * T_ + t) * H_ + j] = nh;
            if (t == T_ - 1) hid1[(b0 + 1) * H_ + j] = nh;
        }
        __syncthreads();
    }
}

// ---------------------------------------------------------------------------
// Kernel 4: FC GEMM  out[r][v] = sum_h y1[r][h] * fc_W[v][h] + fc_b[v]
// Tile: 128 rows x 96 cols per CTA, k-packed f32x2, W transposed in smem.
// Thread (tx,ty): rows ty*8..+7, cols tx + 16*jj (jj<6).
// ---------------------------------------------------------------------------
__global__ void __launch_bounds__(256, 1)
k_fc(const float* __restrict__ fcW, const float* __restrict__ fcb, float* __restrict__ out) {
    extern __shared__ float sm[];
    float2* wst = (float2*)sm;          // [kp=64][v=96] transposed W pairs (48KB)
    float2* ys  = wst + 64 * 96;        // [row=128][kp=64] y pairs (64KB)
    int tid = threadIdx.x;

    const float2* Wg = (const float2*)fcW;
    for (int m = tid; m < 96 * 64; m += 256) {
        int v = m >> 6, kp = m & 63;
        wst[kp * 96 + v] = Wg[m];
    }
    const float4* src = (const float4*)(g_y1 + (size_t)blockIdx.x * 128 * H_);
    float4* ysd = (float4*)ys;
    for (int i = tid; i < 128 * H_ / 4; i += 256) ysd[i] = src[i];
    __syncthreads();

    int tx = tid & 15, ty = tid >> 4;
    ull acc[8][6];
#pragma unroll
    for (int ii = 0; ii < 8; ii++)
#pragma unroll
        for (int jj = 0; jj < 6; jj++) acc[ii][jj] = 0;

    float bfv[6];
#pragma unroll
    for (int jj = 0; jj < 6; jj++) bfv[jj] = fcb[tx + 16 * jj];

    const ull* ysu = (const ull*)ys;
    const ull* wsu = (const ull*)wst;
#pragma unroll 4
    for (int kp = 0; kp < 64; kp++) {
        ull yv[8], wv[6];
#pragma unroll
        for (int ii = 0; ii < 8; ii++) yv[ii] = ysu[(ty * 8 + ii) * 64 + kp];
#pragma unroll
        for (int jj = 0; jj < 6; jj++) wv[jj] = wsu[kp * 96 + tx + 16 * jj];
#pragma unroll
        for (int ii = 0; ii < 8; ii++)
#pragma unroll
            for (int jj = 0; jj < 6; jj++)
                acc[ii][jj] = ffma2(yv[ii], wv[jj], acc[ii][jj]);
    }

    int r0 = blockIdx.x * 128 + ty * 8;
#pragma unroll
    for (int ii = 0; ii < 8; ii++)
#pragma unroll
        for (int jj = 0; jj < 6; jj++)
            out[(size_t)(r0 + ii) * V_ + tx + 16 * jj] = hadd(acc[ii][jj]) + bfv[jj];
}

// ---------------------------------------------------------------------------
extern "C" void kernel_launch(void* const* d_in, const int* in_sizes, int n_in,
                              void* d_out, int out_size) {
    const int*   x    = (const int*)d_in[0];
    const float* emb  = (const float*)d_in[1];
    const float* Wih0 = (const float*)d_in[2];
    const float* Whh0 = (const float*)d_in[3];
    const float* bih0 = (const float*)d_in[4];
    const float* bhh0 = (const float*)d_in[5];
    const float* Wih1 = (const float*)d_in[6];
    const float* Whh1 = (const float*)d_in[7];
    const float* bih1 = (const float*)d_in[8];
    const float* bhh1 = (const float*)d_in[9];
    const float* fcW  = (const float*)d_in[10];
    const float* fcb  = (const float*)d_in[11];

    float* out = (float*)d_out;
    float* hid = out + (size_t)B_ * T_ * V_;   // hidden [2, B, H] after logits

    cudaFuncSetAttribute(k_l0, cudaFuncAttributeMaxDynamicSharedMemorySize, 52224);
    cudaFuncSetAttribute(k_fc, cudaFuncAttributeMaxDynamicSharedMemorySize, 114688);

    k_proj<<<V_, H_>>>(emb, Wih0, bih0, bhh0);
    k_l0<<<B_ / 2, 256, 52224>>>(x, Whh0, hid);
    k_l1<<<B_ / 2, 256>>>(Wih1, Whh1, bih1, bhh1, hid + B_ * H_);
    k_fc<<<(B_ * T_) / 128, 256, 114688>>>(fcW, fcb, out);
}